// round 15
// baseline (speedup 1.0000x reference)
#include <cuda_runtime.h>
#include <cuda_fp16.h>
#include <math.h>
#include <stdint.h>

#define NB 2
#define NT 2048
#define ND 1024
#define NH 16
#define NHD 64
#define NM (NB*NT)   // 4096 rows
#define QSCALE 0.18033688011112042f   // log2(e)/8

// ------------------------- scratch (__device__ globals) ---------------------
__device__ __half g_xh[NM*ND];        // x fp16 / attn-out fp16
__device__ __half g_wh[4*ND*ND];      // Wq,Wk,Wv,Wo fp16
__device__ __half g_qh[NB*NH*NT*NHD];
__device__ __half g_kh[NB*NH*NT*NHD];
__device__ __half g_vh[NB*NH*NT*NHD];

// ------------------------- helpers ------------------------------------------
__device__ __forceinline__ uint32_t smem_u32(const void* p) {
    uint32_t a;
    asm("{ .reg .u64 t; cvta.to.shared.u64 t, %1; cvt.u32.u64 %0, t; }"
        : "=r"(a) : "l"(p));
    return a;
}
__device__ __forceinline__ void cpasync16(uint32_t dst, const void* src) {
    asm volatile("cp.async.ca.shared.global [%0], [%1], 16;" :: "r"(dst), "l"(src));
}
#define CP_COMMIT() asm volatile("cp.async.commit_group;" ::: "memory")

__device__ __forceinline__ void mma16816(float* d, const uint32_t* a, const uint32_t* b) {
    asm volatile("mma.sync.aligned.m16n8k16.row.col.f32.f16.f16.f32 "
        "{%0,%1,%2,%3}, {%4,%5,%6,%7}, {%8,%9}, {%0,%1,%2,%3};"
        : "+f"(d[0]), "+f"(d[1]), "+f"(d[2]), "+f"(d[3])
        : "r"(a[0]), "r"(a[1]), "r"(a[2]), "r"(a[3]), "r"(b[0]), "r"(b[1]));
}
#define LDSM_X4(r0,r1,r2,r3,addr) \
    asm volatile("ldmatrix.sync.aligned.m8n8.x4.shared.b16 {%0,%1,%2,%3}, [%4];" \
        : "=r"(r0), "=r"(r1), "=r"(r2), "=r"(r3) : "r"(addr))
#define LDSM_X4_T(r0,r1,r2,r3,addr) \
    asm volatile("ldmatrix.sync.aligned.m8n8.x4.trans.shared.b16 {%0,%1,%2,%3}, [%4];" \
        : "=r"(r0), "=r"(r1), "=r"(r2), "=r"(r3) : "r"(addr))

// pack two f32 into f16x2 (lo16 = x0)
__device__ __forceinline__ uint32_t pack_f16x2(float x0, float x1) {
    uint32_t r;
    asm("cvt.rn.f16x2.f32 %0, %1, %2;" : "=r"(r) : "f"(x1), "f"(x0));
    return r;
}

// ------------------------- fused fp32 -> fp16 cast ---------------------------
#define WQUARTER (ND*ND/4)            // float4s per weight matrix
__global__ __launch_bounds__(256) void cast_all_kernel(
    const float* __restrict__ w0, const float* __restrict__ w1,
    const float* __restrict__ w2, const float* __restrict__ w3,
    const float* __restrict__ x,
    __half* __restrict__ wh, __half* __restrict__ xh)
{
    int i = blockIdx.x * blockDim.x + threadIdx.x;
    const float* src;
    uint32_t* dst;
    int li;
    if (i < 4 * WQUARTER) {
        int z = i / WQUARTER;
        li = i - z * WQUARTER;
        src = (z == 0) ? w0 : (z == 1) ? w1 : (z == 2) ? w2 : w3;
        dst = (uint32_t*)wh + (size_t)z * (ND*ND/2);
    } else {
        li = i - 4 * WQUARTER;
        if (li >= NM*ND/4) return;
        src = x;
        dst = (uint32_t*)xh;
    }
    float4 v = ((const float4*)src)[li];
    dst[2*li]   = pack_f16x2(v.x, v.y);
    dst[2*li+1] = pack_f16x2(v.z, v.w);
}

// ------------------------- mma.sync fp16 single-pass GEMM --------------------
// Tile 128x128, BK=64, 8 warps (2x4). 128B swizzled rows + ldmatrix fragments.
// 3-stage cp.async ring, 1 sync/stage. 2 CTAs/SM (96KB smem each).
#define GBK 64
#define GTILE 16384
#define GSTAGE (2*GTILE)               // A|B = 32KB
#define GSM_TOTAL (3*GSTAGE)           // 96KB

__global__ __launch_bounds__(256, 2) void tgemm_kernel(
    const __half* __restrict__ ah, const __half* __restrict__ whb,
    const float* __restrict__ b0, const float* __restrict__ b1, const float* __restrict__ b2,
    float* __restrict__ outF,
    __half* __restrict__ h0p, __half* __restrict__ h1p, __half* __restrict__ h2p,
    int modebase, const float* __restrict__ cosp, const float* __restrict__ sinp)
{
    extern __shared__ __align__(128) char smem[];
    const int tid = threadIdx.x;
    const int wid = tid >> 5, lane = tid & 31;
    const int z = blockIdx.z;
    const int bm = blockIdx.y * 128, bn = blockIdx.x * 128;
    const __half* wh = whb + (size_t)z * ND * ND;
    const float* bias = (z == 0) ? b0 : (z == 1) ? b1 : b2;
    __half* hp = (z == 0) ? h0p : (z == 1) ? h1p : h2p;
    const int mode = modebase ? ((z == 2) ? 2 : 1) : 0;
    const float oscale = (modebase && z == 0) ? QSCALE : 1.0f;

    const int wr = wid >> 2;
    const int wc = wid & 3;
    const int g = lane >> 3;
    const int g2 = lane >> 4;

    float acc[4][4][4];
#pragma unroll
    for (int mf = 0; mf < 4; mf++)
#pragma unroll
        for (int nf = 0; nf < 4; nf++)
#pragma unroll
            for (int r = 0; r < 4; r++) acc[mf][nf][r] = 0.f;

    const uint32_t sbase = smem_u32(smem);

    auto stage_load = [&](int buf, int k0) {
        const uint32_t sb = sbase + buf * GSTAGE;
        const __half* srcs[2] = { ah, wh };
#pragma unroll
        for (int tI = 0; tI < 2; tI++) {
            const int rb = (tI == 0) ? bm : bn;
#pragma unroll
            for (int i = 0; i < 4; i++) {
                int c = tid + 256 * i;          // 0..1023
                int r = c >> 3, b16 = (c & 7) * 16;
                uint32_t sw = r * 128 + (b16 ^ ((r & 7) << 4));
                cpasync16(sb + tI * GTILE + sw,
                          srcs[tI] + (size_t)(rb + r) * ND + k0 + b16 / 2);
            }
        }
    };

    stage_load(0, 0);     CP_COMMIT();
    stage_load(1, GBK);   CP_COMMIT();

    const int NS = ND / GBK;   // 16
    for (int st = 0; st < NS; st++) {
        if (st + 1 < NS) { asm volatile("cp.async.wait_group 1;" ::: "memory"); }
        else             { asm volatile("cp.async.wait_group 0;" ::: "memory"); }
        __syncthreads();
        if (st + 2 < NS) { stage_load((st + 2) % 3, (st + 2) * GBK); CP_COMMIT(); }

        const uint32_t sg = sbase + (st % 3) * GSTAGE;

#pragma unroll
        for (int kf = 0; kf < 4; kf++) {
            uint32_t Ah4[4][4], Bh4[4][2];
#pragma unroll
            for (int mf = 0; mf < 4; mf++) {
                const int row = wr * 64 + mf * 16 + (lane & 15);
                const uint32_t byte_ = (uint32_t)(((kf << 5) + (g2 << 4)) ^ ((row & 7) << 4));
                const uint32_t a = sg + row * 128 + byte_;
                LDSM_X4(Ah4[mf][0], Ah4[mf][1], Ah4[mf][2], Ah4[mf][3], a);
            }
            const int rbase = ((g >> 1) << 3) + (lane & 7);
            const uint32_t bbyte = (uint32_t)(((kf << 5) + ((g & 1) << 4)) ^ ((lane & 7) << 4));
#pragma unroll
            for (int nfp = 0; nfp < 2; nfp++) {
                const int row = wc * 32 + nfp * 16 + rbase;
                const uint32_t a = sg + GTILE + row * 128 + bbyte;
                LDSM_X4(Bh4[2*nfp][0], Bh4[2*nfp][1], Bh4[2*nfp+1][0], Bh4[2*nfp+1][1], a);
            }
#pragma unroll
            for (int mf = 0; mf < 4; mf++)
#pragma unroll
                for (int nf = 0; nf < 4; nf++)
                    mma16816(acc[mf][nf], Ah4[mf], Bh4[nf]);
        }
    }

    // ------------- epilogue -------------
#pragma unroll
    for (int mf = 0; mf < 4; mf++) {
#pragma unroll
        for (int h8 = 0; h8 < 2; h8++) {
            const int grow = bm + wr * 64 + mf * 16 + (lane >> 2) + h8 * 8;
            const int bb = grow >> 11, t = grow & (NT - 1);
#pragma unroll
            for (int nf = 0; nf < 4; nf++) {
                const int gcol = bn + wc * 32 + nf * 8 + 2 * (lane & 3);
                float ve = acc[mf][nf][2*h8]   + bias[gcol];
                float vo = acc[mf][nf][2*h8+1] + bias[gcol + 1];
                if (mode == 0) {
                    *(float2*)(outF + (size_t)grow * ND + gcol) = make_float2(ve, vo);
                } else {
                    const int h = gcol >> 6;
                    const int dd = gcol & 63;
                    float y0 = ve, y1 = vo;
                    if (mode == 1) {
                        const int pp = dd >> 1;
                        float cv = cosp[t * 32 + pp];
                        float sv = sinp[t * 32 + pp];
                        y0 = ve * cv - vo * sv;
                        y1 = ve * sv + vo * cv;
                    }
                    size_t idx = (((size_t)bb * NH + h) * NT + t) * NHD + dd;
                    *(uint32_t*)(hp + idx) = pack_f16x2(y0 * oscale, y1 * oscale);
                }
            }
        }
    }
}

// ------------------------- tensor-core flash attention -----------------------
// BQ=128, BKT=64, 8 warps. Single-pass fp16: S = Qh x Kh (32 MMA), PV = Ph x Vh
// (32 MMA), lsum via P x ones MMA (4). 6-buffer KV ring (16KB/stage) + Q 16KB.
// One sync per pair of kt tiles. Q fragments reloaded from smem per kt (4 LDSM)
// so peak live regs fit __launch_bounds__(256,2) -> 2 CTAs/SM.
#define ATT_STAGE 16384
#define ATT_QOFF  (6*ATT_STAGE)        // 98304
#define ATT_SMEM  (ATT_QOFF + 16384)   // 114688 (x2 CTAs = 224KB)

__global__ __launch_bounds__(256, 2) void fattn_kernel(
    const __half* __restrict__ Qh, const __half* __restrict__ Kh,
    const __half* __restrict__ Vh,
    __half* __restrict__ Xh)
{
    extern __shared__ __align__(128) char smem[];
    const int tid = threadIdx.x;
    const int w = tid >> 5, lane = tid & 31;
    const int fr = lane >> 2, fc = lane & 3;
    const int qt = (int)gridDim.x - 1 - (int)blockIdx.x;   // heavy tiles first
    const int hh = blockIdx.y, bb = blockIdx.z;
    const size_t pbase = ((size_t)bb * NH + hh) * NT * NHD;
    const size_t qbase = pbase + (size_t)qt * 128 * NHD;
    const uint32_t sb = smem_u32(smem);

    const int nkt = 2 * qt + 2;

    auto load_kv = [&](int kt_, int buf) {
        const uint32_t db = sb + buf * ATT_STAGE;
        const size_t src = pbase + (size_t)kt_ * 64 * NHD;
#pragma unroll
        for (int i = 0; i < 2; i++) {
            int c = tid + 256 * i;              // 0..511
            int r = c >> 3, b16 = (c & 7) * 16;
            uint32_t sw = r * 128 + (b16 ^ ((r & 7) << 4));
            size_t gs = src + r * 64 + b16 / 2;
            cpasync16(db + sw,        Kh + gs);
            cpasync16(db + 8192 + sw, Vh + gs);
        }
    };

    // ---- prologue: Q (1 group) + kt0..3 into bufs 0..3 ----
#pragma unroll
    for (int i = 0; i < 4; i++) {
        int c = tid + 256 * i;                  // 0..1023
        int r = c >> 3, b16 = (c & 7) * 16;
        uint32_t sw = r * 128 + (b16 ^ ((r & 7) << 4));
        cpasync16(sb + ATT_QOFF + sw, Qh + qbase + r * 64 + b16 / 2);
    }
    CP_COMMIT();
    load_kv(0, 0); CP_COMMIT();
    load_kv(1, 1); CP_COMMIT();
    load_kv(2, 2); CP_COMMIT();
    load_kv(3, 3); CP_COMMIT();

    asm volatile("cp.async.wait_group 4;" ::: "memory");   // Q ready
    __syncthreads();

    // Q smem addresses (Q region persists; fragments reloaded per kt)
    const int qrow = 16 * w + (lane & 15);
    const int qg2 = lane >> 4;
    const uint32_t qsm = sb + ATT_QOFF + qrow * 128;
    const uint32_t qxor = (uint32_t)((qrow & 7) << 4);

    float acc[8][4];
#pragma unroll
    for (int nf = 0; nf < 8; nf++)
#pragma unroll
        for (int r = 0; r < 4; r++) acc[nf][r] = 0.f;
    float accL[4] = {0.f, 0.f, 0.f, 0.f};     // row sums via P x ones
    const uint32_t ones2[2] = { 0x3C003C00u, 0x3C003C00u };

    const int g = lane >> 3;
    const int bxor = (lane & 7) << 4;

    for (int p = 0; p < nkt; p += 2) {
        if (p + 2 < nkt) { asm volatile("cp.async.wait_group 2;" ::: "memory"); }
        else             { asm volatile("cp.async.wait_group 0;" ::: "memory"); }
        __syncthreads();    // all warps done with pair p-2
        if (p + 4 < nkt) { load_kv(p + 4, (p + 4) % 6); CP_COMMIT(); }
        if (p + 5 < nkt) { load_kv(p + 5, (p + 5) % 6); CP_COMMIT(); }

#pragma unroll
        for (int sub = 0; sub < 2; sub++) {
            const int kt = p + sub;
            const uint32_t sg = sb + (kt % 6) * ATT_STAGE;
            const bool fullskip = (kt * 64 > qt * 128 + 16 * w + 15);
            if (fullskip) continue;

            // ---------- reload Q fragments (4 LDSM; regs die before PV) ----
            uint32_t QHf[4][4];
#pragma unroll
            for (int kf = 0; kf < 4; kf++) {
                uint32_t byte_ = (uint32_t)((kf * 32 + qg2 * 16) ^ qxor);
                LDSM_X4(QHf[kf][0], QHf[kf][1], QHf[kf][2], QHf[kf][3], qsm + byte_);
            }

            // ---------- S = Q K^T (single pass) ----------
            float Sy[8][4];
#pragma unroll
            for (int nf = 0; nf < 8; nf++)
#pragma unroll
                for (int r = 0; r < 4; r++) Sy[nf][r] = 0.f;

#pragma unroll
            for (int kf = 0; kf < 4; kf++) {
                uint32_t KBh[8][2];
                const int rbase = ((g >> 1) << 3) + (lane & 7);
                const uint32_t byte_ = (uint32_t)(((kf << 5) + ((g & 1) << 4)) ^ bxor);
#pragma unroll
                for (int nfp = 0; nfp < 4; nfp++) {
                    uint32_t a = sg + (nfp * 16 + rbase) * 128 + byte_;
                    LDSM_X4(KBh[2*nfp][0], KBh[2*nfp][1], KBh[2*nfp+1][0], KBh[2*nfp+1][1], a);
                }
#pragma unroll
                for (int nf = 0; nf < 8; nf++) mma16816(Sy[nf], QHf[kf], KBh[nf]);
            }

            // ---------- causal mask (diagonal tiles only) ----------
            if (kt * 64 + 63 > qt * 128 + 16 * w) {
                const int gr0 = qt * 128 + 16 * w + fr;
#pragma unroll
                for (int nf = 0; nf < 8; nf++) {
                    const int gc = kt * 64 + 8 * nf + 2 * fc;
#pragma unroll
                    for (int r = 0; r < 4; r++) {
                        const int row = gr0 + ((r >> 1) << 3);
                        const int col = gc + (r & 1);
                        if (col > row) Sy[nf][r] = -60.f;
                    }
                }
            }

            // ---------- exp2 (deg-4 poly; lsum via MMA below) ----------
#pragma unroll
            for (int nf = 0; nf < 8; nf++) {
#pragma unroll
                for (int r = 0; r < 4; r++) {
                    float y = Sy[nf][r];
                    float t = y + 12582912.f;
                    float f = y - (t - 12582912.f);
                    int sh = (int)(__float_as_uint(t) << 23);
                    float p2 = fmaf(f, 0.00961813f, 0.05550411f);
                    p2 = fmaf(f, p2, 0.24022651f);
                    p2 = fmaf(f, p2, 0.69314718f);
                    p2 = fmaf(f, p2, 1.0f);
                    Sy[nf][r] = __int_as_float(__float_as_int(p2) + sh);
                }
            }

            // ---------- per-pair pack + lsum MMA + PV (single pass) ----------
#pragma unroll
            for (int kf2 = 0; kf2 < 4; kf2++) {
                uint32_t PHf[4];
                PHf[0] = pack_f16x2(Sy[2*kf2][0],   Sy[2*kf2][1]);
                PHf[1] = pack_f16x2(Sy[2*kf2][2],   Sy[2*kf2][3]);
                PHf[2] = pack_f16x2(Sy[2*kf2+1][0], Sy[2*kf2+1][1]);
                PHf[3] = pack_f16x2(Sy[2*kf2+1][2], Sy[2*kf2+1][3]);

                mma16816(accL, PHf, ones2);   // row sums of this 16-key chunk

                uint32_t VBh[8][2];
                const int rv = (kf2 << 4) + ((g & 1) << 3) + (lane & 7);
                const uint32_t vb0 = sg + 8192 + rv * 128;
#pragma unroll
                for (int nfp = 0; nfp < 4; nfp++) {
                    uint32_t byte_ = (uint32_t)(((2*nfp + (g >> 1)) << 4) ^ bxor);
                    LDSM_X4_T(VBh[2*nfp][0], VBh[2*nfp][1], VBh[2*nfp+1][0], VBh[2*nfp+1][1], vb0 + byte_);
                }
#pragma unroll
                for (int nf = 0; nf < 8; nf++) mma16816(acc[nf], PHf, VBh[nf]);
            }
        }
    }

    // ---------- finalize: write fp16 plane for O-projection ----------
    const float i0 = 1.f / accL[0];
    const float i1 = 1.f / accL[2];

    const int row0 = qt * 128 + 16 * w + fr;
    const size_t idx0 = ((size_t)(bb * NT + row0)) * ND + hh * 64;
    const size_t idx1 = idx0 + (size_t)8 * ND;
#pragma unroll
    for (int nf = 0; nf < 8; nf++) {
        *(uint32_t*)(Xh + idx0 + 8*nf + 2*fc) = pack_f16x2(acc[nf][0] * i0, acc[nf][1] * i0);
        *(uint32_t*)(Xh + idx1 + 8*nf + 2*fc) = pack_f16x2(acc[nf][2] * i1, acc[nf][3] * i1);
    }
}

// ---------------------------------------------------------------------------
extern "C" void kernel_launch(void* const* d_in, const int* in_sizes, int n_in,
                              void* d_out, int out_size)
{
    (void)in_sizes; (void)n_in; (void)out_size;
    const float* x    = (const float*)d_in[0];
    const float* cosp = (const float*)d_in[1];
    const float* sinp = (const float*)d_in[2];
    const float* Wq   = (const float*)d_in[3];
    const float* bq   = (const float*)d_in[4];
    const float* Wk   = (const float*)d_in[5];
    const float* bk   = (const float*)d_in[6];
    const float* Wv   = (const float*)d_in[7];
    const float* bv   = (const float*)d_in[8];
    const float* Wo   = (const float*)d_in[9];
    const float* bo   = (const float*)d_in[10];
    float* out = (float*)d_out;

    __half *xh, *wh, *qh, *kh, *vh;
    cudaGetSymbolAddress((void**)&xh, g_xh);
    cudaGetSymbolAddress((void**)&wh, g_wh);
    cudaGetSymbolAddress((void**)&qh, g_qh);
    cudaGetSymbolAddress((void**)&kh, g_kh);
    cudaGetSymbolAddress((void**)&vh, g_vh);

    cudaFuncSetAttribute(tgemm_kernel,
                         cudaFuncAttributeMaxDynamicSharedMemorySize, GSM_TOTAL);
    cudaFuncSetAttribute(fattn_kernel,
                         cudaFuncAttributeMaxDynamicSharedMemorySize, ATT_SMEM);

    // fused cast: 4 weights + x in one launch
    const int ncast4 = 4 * WQUARTER + NM*ND/4;
    cast_all_kernel<<<(ncast4 + 255)/256, 256>>>(Wq, Wk, Wv, Wo, x, wh, xh);

    // QKV projection (single-pass fp16): Q RoPE+scale, K RoPE, V plain
    tgemm_kernel<<<dim3(ND/128, NM/128, 3), 256, GSM_TOTAL>>>(
        xh, wh, bq, bk, bv, nullptr,
        qh, kh, vh, 1, cosp, sinp);

    // tensor-core flash attention -> fp16 plane (overwrites xh)
    fattn_kernel<<<dim3(NT/128, NH, NB), 256, ATT_SMEM>>>(
        qh, kh, vh, xh);

    // O projection (single-pass fp16, fp32 out)
    tgemm_kernel<<<dim3(ND/128, NM/128, 1), 256, GSM_TOTAL>>>(
        xh, wh + (size_t)3*ND*ND, bo, bo, bo, out,
        nullptr, nullptr, nullptr, 0, nullptr, nullptr);
}

// round 16
// speedup vs baseline: 1.0289x; 1.0289x over previous
#include <cuda_runtime.h>
#include <cuda_fp16.h>
#include <math.h>
#include <stdint.h>

#define NB 2
#define NT 2048
#define ND 1024
#define NH 16
#define NHD 64
#define NM (NB*NT)   // 4096 rows
#define QSCALE 0.18033688011112042f   // log2(e)/8

// ------------------------- scratch (__device__ globals) ---------------------
__device__ __half g_xh[NM*ND];        // x fp16 / attn-out fp16
__device__ __half g_wh[4*ND*ND];      // Wq,Wk,Wv,Wo fp16
__device__ __half g_qh[NB*NH*NT*NHD];
__device__ __half g_kh[NB*NH*NT*NHD];
__device__ __half g_vh[NB*NH*NT*NHD];

// ------------------------- helpers ------------------------------------------
__device__ __forceinline__ uint32_t smem_u32(const void* p) {
    uint32_t a;
    asm("{ .reg .u64 t; cvta.to.shared.u64 t, %1; cvt.u32.u64 %0, t; }"
        : "=r"(a) : "l"(p));
    return a;
}
__device__ __forceinline__ void cpasync16(uint32_t dst, const void* src) {
    asm volatile("cp.async.ca.shared.global [%0], [%1], 16;" :: "r"(dst), "l"(src));
}
#define CP_COMMIT() asm volatile("cp.async.commit_group;" ::: "memory")

__device__ __forceinline__ void mma16816(float* d, const uint32_t* a, const uint32_t* b) {
    asm volatile("mma.sync.aligned.m16n8k16.row.col.f32.f16.f16.f32 "
        "{%0,%1,%2,%3}, {%4,%5,%6,%7}, {%8,%9}, {%0,%1,%2,%3};"
        : "+f"(d[0]), "+f"(d[1]), "+f"(d[2]), "+f"(d[3])
        : "r"(a[0]), "r"(a[1]), "r"(a[2]), "r"(a[3]), "r"(b[0]), "r"(b[1]));
}
#define LDSM_X4(r0,r1,r2,r3,addr) \
    asm volatile("ldmatrix.sync.aligned.m8n8.x4.shared.b16 {%0,%1,%2,%3}, [%4];" \
        : "=r"(r0), "=r"(r1), "=r"(r2), "=r"(r3) : "r"(addr))
#define LDSM_X4_T(r0,r1,r2,r3,addr) \
    asm volatile("ldmatrix.sync.aligned.m8n8.x4.trans.shared.b16 {%0,%1,%2,%3}, [%4];" \
        : "=r"(r0), "=r"(r1), "=r"(r2), "=r"(r3) : "r"(addr))

// pack two f32 into f16x2 (lo16 = x0)
__device__ __forceinline__ uint32_t pack_f16x2(float x0, float x1) {
    uint32_t r;
    asm("cvt.rn.f16x2.f32 %0, %1, %2;" : "=r"(r) : "f"(x1), "f"(x0));
    return r;
}

// ------------------------- fused fp32 -> fp16 cast ---------------------------
#define WQUARTER (ND*ND/4)            // float4s per weight matrix
__global__ __launch_bounds__(256) void cast_all_kernel(
    const float* __restrict__ w0, const float* __restrict__ w1,
    const float* __restrict__ w2, const float* __restrict__ w3,
    const float* __restrict__ x,
    __half* __restrict__ wh, __half* __restrict__ xh)
{
    int i = blockIdx.x * blockDim.x + threadIdx.x;
    const float* src;
    uint32_t* dst;
    int li;
    if (i < 4 * WQUARTER) {
        int z = i / WQUARTER;
        li = i - z * WQUARTER;
        src = (z == 0) ? w0 : (z == 1) ? w1 : (z == 2) ? w2 : w3;
        dst = (uint32_t*)wh + (size_t)z * (ND*ND/2);
    } else {
        li = i - 4 * WQUARTER;
        if (li >= NM*ND/4) return;
        src = x;
        dst = (uint32_t*)xh;
    }
    float4 v = ((const float4*)src)[li];
    dst[2*li]   = pack_f16x2(v.x, v.y);
    dst[2*li+1] = pack_f16x2(v.z, v.w);
}

// ------------------------- mma.sync fp16 single-pass GEMM --------------------
// Tile 128x128, BK=64, 8 warps (2x4). 128B swizzled rows + ldmatrix fragments.
// 3-stage cp.async ring, 1 sync/stage. 2 CTAs/SM (96KB smem each).
#define GBK 64
#define GTILE 16384
#define GSTAGE (2*GTILE)               // A|B = 32KB
#define GSM_TOTAL (3*GSTAGE)           // 96KB

__global__ __launch_bounds__(256, 2) void tgemm_kernel(
    const __half* __restrict__ ah, const __half* __restrict__ whb,
    const float* __restrict__ b0, const float* __restrict__ b1, const float* __restrict__ b2,
    float* __restrict__ outF,
    __half* __restrict__ h0p, __half* __restrict__ h1p, __half* __restrict__ h2p,
    int modebase, const float* __restrict__ cosp, const float* __restrict__ sinp)
{
    extern __shared__ __align__(128) char smem[];
    const int tid = threadIdx.x;
    const int wid = tid >> 5, lane = tid & 31;
    const int z = blockIdx.z;
    const int bm = blockIdx.y * 128, bn = blockIdx.x * 128;
    const __half* wh = whb + (size_t)z * ND * ND;
    const float* bias = (z == 0) ? b0 : (z == 1) ? b1 : b2;
    __half* hp = (z == 0) ? h0p : (z == 1) ? h1p : h2p;
    const int mode = modebase ? ((z == 2) ? 2 : 1) : 0;
    const float oscale = (modebase && z == 0) ? QSCALE : 1.0f;

    const int wr = wid >> 2;
    const int wc = wid & 3;
    const int g = lane >> 3;
    const int g2 = lane >> 4;

    float acc[4][4][4];
#pragma unroll
    for (int mf = 0; mf < 4; mf++)
#pragma unroll
        for (int nf = 0; nf < 4; nf++)
#pragma unroll
            for (int r = 0; r < 4; r++) acc[mf][nf][r] = 0.f;

    const uint32_t sbase = smem_u32(smem);

    auto stage_load = [&](int buf, int k0) {
        const uint32_t sb = sbase + buf * GSTAGE;
        const __half* srcs[2] = { ah, wh };
#pragma unroll
        for (int tI = 0; tI < 2; tI++) {
            const int rb = (tI == 0) ? bm : bn;
#pragma unroll
            for (int i = 0; i < 4; i++) {
                int c = tid + 256 * i;          // 0..1023
                int r = c >> 3, b16 = (c & 7) * 16;
                uint32_t sw = r * 128 + (b16 ^ ((r & 7) << 4));
                cpasync16(sb + tI * GTILE + sw,
                          srcs[tI] + (size_t)(rb + r) * ND + k0 + b16 / 2);
            }
        }
    };

    stage_load(0, 0);     CP_COMMIT();
    stage_load(1, GBK);   CP_COMMIT();

    const int NS = ND / GBK;   // 16
    for (int st = 0; st < NS; st++) {
        if (st + 1 < NS) { asm volatile("cp.async.wait_group 1;" ::: "memory"); }
        else             { asm volatile("cp.async.wait_group 0;" ::: "memory"); }
        __syncthreads();
        if (st + 2 < NS) { stage_load((st + 2) % 3, (st + 2) * GBK); CP_COMMIT(); }

        const uint32_t sg = sbase + (st % 3) * GSTAGE;

#pragma unroll
        for (int kf = 0; kf < 4; kf++) {
            uint32_t Ah4[4][4], Bh4[4][2];
#pragma unroll
            for (int mf = 0; mf < 4; mf++) {
                const int row = wr * 64 + mf * 16 + (lane & 15);
                const uint32_t byte_ = (uint32_t)(((kf << 5) + (g2 << 4)) ^ ((row & 7) << 4));
                const uint32_t a = sg + row * 128 + byte_;
                LDSM_X4(Ah4[mf][0], Ah4[mf][1], Ah4[mf][2], Ah4[mf][3], a);
            }
            const int rbase = ((g >> 1) << 3) + (lane & 7);
            const uint32_t bbyte = (uint32_t)(((kf << 5) + ((g & 1) << 4)) ^ ((lane & 7) << 4));
#pragma unroll
            for (int nfp = 0; nfp < 2; nfp++) {
                const int row = wc * 32 + nfp * 16 + rbase;
                const uint32_t a = sg + GTILE + row * 128 + bbyte;
                LDSM_X4(Bh4[2*nfp][0], Bh4[2*nfp][1], Bh4[2*nfp+1][0], Bh4[2*nfp+1][1], a);
            }
#pragma unroll
            for (int mf = 0; mf < 4; mf++)
#pragma unroll
                for (int nf = 0; nf < 4; nf++)
                    mma16816(acc[mf][nf], Ah4[mf], Bh4[nf]);
        }
    }

    // ------------- epilogue -------------
#pragma unroll
    for (int mf = 0; mf < 4; mf++) {
#pragma unroll
        for (int h8 = 0; h8 < 2; h8++) {
            const int grow = bm + wr * 64 + mf * 16 + (lane >> 2) + h8 * 8;
            const int bb = grow >> 11, t = grow & (NT - 1);
#pragma unroll
            for (int nf = 0; nf < 4; nf++) {
                const int gcol = bn + wc * 32 + nf * 8 + 2 * (lane & 3);
                float ve = acc[mf][nf][2*h8]   + bias[gcol];
                float vo = acc[mf][nf][2*h8+1] + bias[gcol + 1];
                if (mode == 0) {
                    *(float2*)(outF + (size_t)grow * ND + gcol) = make_float2(ve, vo);
                } else {
                    const int h = gcol >> 6;
                    const int dd = gcol & 63;
                    float y0 = ve, y1 = vo;
                    if (mode == 1) {
                        const int pp = dd >> 1;
                        float cv = cosp[t * 32 + pp];
                        float sv = sinp[t * 32 + pp];
                        y0 = ve * cv - vo * sv;
                        y1 = ve * sv + vo * cv;
                    }
                    size_t idx = (((size_t)bb * NH + h) * NT + t) * NHD + dd;
                    *(uint32_t*)(hp + idx) = pack_f16x2(y0 * oscale, y1 * oscale);
                }
            }
        }
    }
}

// ------------------------- tensor-core flash attention -----------------------
// BQ=128, BKT=64, 8 warps, 1 CTA/SM, Q frags resident in registers.
// Single-pass fp16. 6-buffer KV ring + Q, one sync per pair of kt tiles.
// NEW: double-buffered K/V fragment prefetch — LDSM for step i+1 issues before
// the MMAs of step i, hiding smem-return latency inside the MMA drain.
#define ATT_STAGE 16384
#define ATT_QOFF  (6*ATT_STAGE)        // 98304
#define ATT_SMEM  (ATT_QOFF + 16384)   // 114688

__global__ __launch_bounds__(256, 1) void fattn_kernel(
    const __half* __restrict__ Qh, const __half* __restrict__ Kh,
    const __half* __restrict__ Vh,
    __half* __restrict__ Xh)
{
    extern __shared__ __align__(128) char smem[];
    const int tid = threadIdx.x;
    const int w = tid >> 5, lane = tid & 31;
    const int fr = lane >> 2, fc = lane & 3;
    const int qt = (int)gridDim.x - 1 - (int)blockIdx.x;   // heavy tiles first
    const int hh = blockIdx.y, bb = blockIdx.z;
    const size_t pbase = ((size_t)bb * NH + hh) * NT * NHD;
    const size_t qbase = pbase + (size_t)qt * 128 * NHD;
    const uint32_t sb = smem_u32(smem);

    const int nkt = 2 * qt + 2;

    auto load_kv = [&](int kt_, int buf) {
        const uint32_t db = sb + buf * ATT_STAGE;
        const size_t src = pbase + (size_t)kt_ * 64 * NHD;
#pragma unroll
        for (int i = 0; i < 2; i++) {
            int c = tid + 256 * i;              // 0..511
            int r = c >> 3, b16 = (c & 7) * 16;
            uint32_t sw = r * 128 + (b16 ^ ((r & 7) << 4));
            size_t gs = src + r * 64 + b16 / 2;
            cpasync16(db + sw,        Kh + gs);
            cpasync16(db + 8192 + sw, Vh + gs);
        }
    };

    // ---- prologue: Q (1 group) + kt0..3 into bufs 0..3 ----
#pragma unroll
    for (int i = 0; i < 4; i++) {
        int c = tid + 256 * i;                  // 0..1023
        int r = c >> 3, b16 = (c & 7) * 16;
        uint32_t sw = r * 128 + (b16 ^ ((r & 7) << 4));
        cpasync16(sb + ATT_QOFF + sw, Qh + qbase + r * 64 + b16 / 2);
    }
    CP_COMMIT();
    load_kv(0, 0); CP_COMMIT();
    load_kv(1, 1); CP_COMMIT();
    load_kv(2, 2); CP_COMMIT();
    load_kv(3, 3); CP_COMMIT();

    asm volatile("cp.async.wait_group 4;" ::: "memory");   // Q ready
    __syncthreads();

    uint32_t QHf[4][4];
    {
        int r = 16 * w + (lane & 15);
        int g2 = lane >> 4;
#pragma unroll
        for (int kf = 0; kf < 4; kf++) {
            uint32_t byte_ = (uint32_t)((kf * 32 + g2 * 16) ^ ((r & 7) << 4));
            uint32_t a = sb + ATT_QOFF + r * 128 + byte_;
            LDSM_X4(QHf[kf][0], QHf[kf][1], QHf[kf][2], QHf[kf][3], a);
        }
    }

    float acc[8][4];
#pragma unroll
    for (int nf = 0; nf < 8; nf++)
#pragma unroll
        for (int r = 0; r < 4; r++) acc[nf][r] = 0.f;
    float accL[4] = {0.f, 0.f, 0.f, 0.f};     // row sums via P x ones
    const uint32_t ones2[2] = { 0x3C003C00u, 0x3C003C00u };

    const int g = lane >> 3;
    const int bxor = (lane & 7) << 4;
    const int rbase = ((g >> 1) << 3) + (lane & 7);

    for (int p = 0; p < nkt; p += 2) {
        if (p + 2 < nkt) { asm volatile("cp.async.wait_group 2;" ::: "memory"); }
        else             { asm volatile("cp.async.wait_group 0;" ::: "memory"); }
        __syncthreads();    // all warps done with pair p-2; Q read done (p=0)
        if (p + 4 < nkt) { load_kv(p + 4, (p + 4) % 6); CP_COMMIT(); }
        if (p + 5 < nkt) { load_kv(p + 5, (p + 5) % 6); CP_COMMIT(); }

#pragma unroll
        for (int sub = 0; sub < 2; sub++) {
            const int kt = p + sub;
            const uint32_t sg = sb + (kt % 6) * ATT_STAGE;
            const bool fullskip = (kt * 64 > qt * 128 + 16 * w + 15);
            if (fullskip) continue;

            // ---------- S = Q K^T with double-buffered K frag prefetch ----
            float Sy[8][4];
#pragma unroll
            for (int nf = 0; nf < 8; nf++)
#pragma unroll
                for (int r = 0; r < 4; r++) Sy[nf][r] = 0.f;

            uint32_t KB[2][8][2];
            {
                const uint32_t byte0 = (uint32_t)((((g & 1) << 4)) ^ bxor);
#pragma unroll
                for (int nfp = 0; nfp < 4; nfp++) {
                    uint32_t a = sg + (nfp * 16 + rbase) * 128 + byte0;
                    LDSM_X4(KB[0][2*nfp][0], KB[0][2*nfp][1],
                            KB[0][2*nfp+1][0], KB[0][2*nfp+1][1], a);
                }
            }
#pragma unroll
            for (int kf = 0; kf < 4; kf++) {
                if (kf < 3) {
                    const uint32_t byte_ =
                        (uint32_t)((((kf + 1) << 5) + ((g & 1) << 4)) ^ bxor);
#pragma unroll
                    for (int nfp = 0; nfp < 4; nfp++) {
                        uint32_t a = sg + (nfp * 16 + rbase) * 128 + byte_;
                        LDSM_X4(KB[(kf+1)&1][2*nfp][0], KB[(kf+1)&1][2*nfp][1],
                                KB[(kf+1)&1][2*nfp+1][0], KB[(kf+1)&1][2*nfp+1][1], a);
                    }
                }
#pragma unroll
                for (int nf = 0; nf < 8; nf++)
                    mma16816(Sy[nf], QHf[kf], KB[kf&1][nf]);
            }

            // ---------- causal mask (diagonal tiles only) ----------
            if (kt * 64 + 63 > qt * 128 + 16 * w) {
                const int gr0 = qt * 128 + 16 * w + fr;
#pragma unroll
                for (int nf = 0; nf < 8; nf++) {
                    const int gc = kt * 64 + 8 * nf + 2 * fc;
#pragma unroll
                    for (int r = 0; r < 4; r++) {
                        const int row = gr0 + ((r >> 1) << 3);
                        const int col = gc + (r & 1);
                        if (col > row) Sy[nf][r] = -60.f;
                    }
                }
            }

            // ---------- exp2 (deg-4 poly) ----------
#pragma unroll
            for (int nf = 0; nf < 8; nf++) {
#pragma unroll
                for (int r = 0; r < 4; r++) {
                    float y = Sy[nf][r];
                    float t = y + 12582912.f;
                    float f = y - (t - 12582912.f);
                    int sh = (int)(__float_as_uint(t) << 23);
                    float p2 = fmaf(f, 0.00961813f, 0.05550411f);
                    p2 = fmaf(f, p2, 0.24022651f);
                    p2 = fmaf(f, p2, 0.69314718f);
                    p2 = fmaf(f, p2, 1.0f);
                    Sy[nf][r] = __int_as_float(__float_as_int(p2) + sh);
                }
            }

            // ---------- pack all P (overlaps first V LDSM below) ----------
            uint32_t PH[4][4];
#pragma unroll
            for (int kf2 = 0; kf2 < 4; kf2++) {
                PH[kf2][0] = pack_f16x2(Sy[2*kf2][0],   Sy[2*kf2][1]);
                PH[kf2][1] = pack_f16x2(Sy[2*kf2][2],   Sy[2*kf2][3]);
                PH[kf2][2] = pack_f16x2(Sy[2*kf2+1][0], Sy[2*kf2+1][1]);
                PH[kf2][3] = pack_f16x2(Sy[2*kf2+1][2], Sy[2*kf2+1][3]);
            }

            // ---------- PV with double-buffered V frag prefetch ----------
            uint32_t VB[2][8][2];
            {
                const int rv = ((g & 1) << 3) + (lane & 7);   // kf2 = 0
                const uint32_t vb0 = sg + 8192 + rv * 128;
#pragma unroll
                for (int nfp = 0; nfp < 4; nfp++) {
                    uint32_t byte_ = (uint32_t)(((2*nfp + (g >> 1)) << 4) ^ bxor);
                    LDSM_X4_T(VB[0][2*nfp][0], VB[0][2*nfp][1],
                              VB[0][2*nfp+1][0], VB[0][2*nfp+1][1], vb0 + byte_);
                }
            }
#pragma unroll
            for (int kf2 = 0; kf2 < 4; kf2++) {
                if (kf2 < 3) {
                    const int rv = ((kf2 + 1) << 4) + ((g & 1) << 3) + (lane & 7);
                    const uint32_t vb0 = sg + 8192 + rv * 128;
#pragma unroll
                    for (int nfp = 0; nfp < 4; nfp++) {
                        uint32_t byte_ = (uint32_t)(((2*nfp + (g >> 1)) << 4) ^ bxor);
                        LDSM_X4_T(VB[(kf2+1)&1][2*nfp][0], VB[(kf2+1)&1][2*nfp][1],
                                  VB[(kf2+1)&1][2*nfp+1][0], VB[(kf2+1)&1][2*nfp+1][1],
                                  vb0 + byte_);
                    }
                }
                mma16816(accL, PH[kf2], ones2);   // row sums of this 16-key chunk
#pragma unroll
                for (int nf = 0; nf < 8; nf++)
                    mma16816(acc[nf], PH[kf2], VB[kf2&1][nf]);
            }
        }
    }

    // ---------- finalize: write fp16 plane for O-projection ----------
    const float i0 = 1.f / accL[0];
    const float i1 = 1.f / accL[2];

    const int row0 = qt * 128 + 16 * w + fr;
    const size_t idx0 = ((size_t)(bb * NT + row0)) * ND + hh * 64;
    const size_t idx1 = idx0 + (size_t)8 * ND;
#pragma unroll
    for (int nf = 0; nf < 8; nf++) {
        *(uint32_t*)(Xh + idx0 + 8*nf + 2*fc) = pack_f16x2(acc[nf][0] * i0, acc[nf][1] * i0);
        *(uint32_t*)(Xh + idx1 + 8*nf + 2*fc) = pack_f16x2(acc[nf][2] * i1, acc[nf][3] * i1);
    }
}

// ---------------------------------------------------------------------------
extern "C" void kernel_launch(void* const* d_in, const int* in_sizes, int n_in,
                              void* d_out, int out_size)
{
    (void)in_sizes; (void)n_in; (void)out_size;
    const float* x    = (const float*)d_in[0];
    const float* cosp = (const float*)d_in[1];
    const float* sinp = (const float*)d_in[2];
    const float* Wq   = (const float*)d_in[3];
    const float* bq   = (const float*)d_in[4];
    const float* Wk   = (const float*)d_in[5];
    const float* bk   = (const float*)d_in[6];
    const float* Wv   = (const float*)d_in[7];
    const float* bv   = (const float*)d_in[8];
    const float* Wo   = (const float*)d_in[9];
    const float* bo   = (const float*)d_in[10];
    float* out = (float*)d_out;

    __half *xh, *wh, *qh, *kh, *vh;
    cudaGetSymbolAddress((void**)&xh, g_xh);
    cudaGetSymbolAddress((void**)&wh, g_wh);
    cudaGetSymbolAddress((void**)&qh, g_qh);
    cudaGetSymbolAddress((void**)&kh, g_kh);
    cudaGetSymbolAddress((void**)&vh, g_vh);

    cudaFuncSetAttribute(tgemm_kernel,
                         cudaFuncAttributeMaxDynamicSharedMemorySize, GSM_TOTAL);
    cudaFuncSetAttribute(fattn_kernel,
                         cudaFuncAttributeMaxDynamicSharedMemorySize, ATT_SMEM);

    // fused cast: 4 weights + x in one launch
    const int ncast4 = 4 * WQUARTER + NM*ND/4;
    cast_all_kernel<<<(ncast4 + 255)/256, 256>>>(Wq, Wk, Wv, Wo, x, wh, xh);

    // QKV projection (single-pass fp16): Q RoPE+scale, K RoPE, V plain
    tgemm_kernel<<<dim3(ND/128, NM/128, 3), 256, GSM_TOTAL>>>(
        xh, wh, bq, bk, bv, nullptr,
        qh, kh, vh, 1, cosp, sinp);

    // tensor-core flash attention -> fp16 plane (overwrites xh)
    fattn_kernel<<<dim3(NT/128, NH, NB), 256, ATT_SMEM>>>(
        qh, kh, vh, xh);

    // O projection (single-pass fp16, fp32 out)
    tgemm_kernel<<<dim3(ND/128, NM/128, 1), 256, GSM_TOTAL>>>(
        xh, wh + (size_t)3*ND*ND, bo, bo, bo, out,
        nullptr, nullptr, nullptr, 0, nullptr, nullptr);
}